// round 10
// baseline (speedup 1.0000x reference)
#include <cuda_runtime.h>
#include <cuda_bf16.h>
#include <cstdint>

#define N_NODES 50000
#define N_EDGES 800000
#define N_GRAPHS 128
#define D 128
#define L_LAYERS 4
#define N_CLASSES 10
#define GN_EPS 1e-5f

#define SCAN_BLK 1024
#define SCAN_NBLK ((N_NODES + SCAN_BLK - 1) / SCAN_BLK)

#define LDT 136   // padded smem row stride in bf16 elements (128 + 8)
#define STP 132   // fp32 stage pitch (16B-aligned float4 rows)

// ---------------- device scratch ----------------------------------------------
__device__ float g_A[N_NODES * D];                     // ping
__device__ float g_B[N_NODES * D];                     // pong
__device__ float g_stats[L_LAYERS * 2 * N_GRAPHS * D]; // per-layer [SUM | SUMSQ]
__device__ int   g_cnt[N_GRAPHS];
__device__ float g_rcnt[N_GRAPHS];
__device__ float g_gsum[N_GRAPHS * D];
__device__ float g_m1[N_GRAPHS * D];
__device__ float g_m2[N_GRAPHS * D];
__device__ int   g_batch[N_NODES];
__device__ int   g_is64;
// CSR
__device__ int   g_indeg[N_NODES];
__device__ int   g_rowptr[N_NODES + 1];
__device__ int   g_cursor[N_NODES];
__device__ int   g_col[N_EDGES];
__device__ int   g_blocksum[SCAN_NBLK];
__device__ int   g_blockoff[SCAN_NBLK];
// prepped weights: 8 matrices x {hi,lo} x [N=128][K=128] bf16 row-major (W^T split)
__device__ __align__(16) __nv_bfloat16 g_wprep[8 * 2 * D * D];

// ---------------- helpers -------------------------------------------------------
__device__ __forceinline__ uint32_t pack_bf16(__nv_bfloat16 a, __nv_bfloat16 b) {
    __nv_bfloat162 t;
    t.x = a; t.y = b;
    return *reinterpret_cast<uint32_t*>(&t);
}

__device__ __forceinline__ void mma16816(float* c, const uint32_t* a, const uint32_t* b) {
    asm volatile(
        "mma.sync.aligned.m16n8k16.row.col.f32.bf16.bf16.f32 "
        "{%0,%1,%2,%3}, {%4,%5,%6,%7}, {%8,%9}, {%0,%1,%2,%3};\n"
        : "+f"(c[0]), "+f"(c[1]), "+f"(c[2]), "+f"(c[3])
        : "r"(a[0]), "r"(a[1]), "r"(a[2]), "r"(a[3]), "r"(b[0]), "r"(b[1]));
}

// split-bf16 MMA mainloop over a resident 128x128 tile pair
__device__ __forceinline__ void mma_loop(const __nv_bfloat16* sAhi, const __nv_bfloat16* sAlo,
                                         const __nv_bfloat16* sBhi, const __nv_bfloat16* sBlo,
                                         int wm, int wn, int g, int t, float acc[2][8][4]) {
#pragma unroll
    for (int ks = 0; ks < 8; ks++) {
        int kb = ks * 16 + t * 2;
        uint32_t ah[2][4], al[2][4];
#pragma unroll
        for (int mi = 0; mi < 2; mi++) {
            int r0 = wm * 32 + mi * 16;
            ah[mi][0] = *reinterpret_cast<const uint32_t*>(&sAhi[(r0 + g) * LDT + kb]);
            ah[mi][1] = *reinterpret_cast<const uint32_t*>(&sAhi[(r0 + g + 8) * LDT + kb]);
            ah[mi][2] = *reinterpret_cast<const uint32_t*>(&sAhi[(r0 + g) * LDT + kb + 8]);
            ah[mi][3] = *reinterpret_cast<const uint32_t*>(&sAhi[(r0 + g + 8) * LDT + kb + 8]);
            al[mi][0] = *reinterpret_cast<const uint32_t*>(&sAlo[(r0 + g) * LDT + kb]);
            al[mi][1] = *reinterpret_cast<const uint32_t*>(&sAlo[(r0 + g + 8) * LDT + kb]);
            al[mi][2] = *reinterpret_cast<const uint32_t*>(&sAlo[(r0 + g) * LDT + kb + 8]);
            al[mi][3] = *reinterpret_cast<const uint32_t*>(&sAlo[(r0 + g + 8) * LDT + kb + 8]);
        }
        uint32_t bh[8][2], bl[8][2];
#pragma unroll
        for (int ni = 0; ni < 8; ni++) {
            int n0 = wn * 64 + ni * 8;
            bh[ni][0] = *reinterpret_cast<const uint32_t*>(&sBhi[(n0 + g) * LDT + kb]);
            bh[ni][1] = *reinterpret_cast<const uint32_t*>(&sBhi[(n0 + g) * LDT + kb + 8]);
            bl[ni][0] = *reinterpret_cast<const uint32_t*>(&sBlo[(n0 + g) * LDT + kb]);
            bl[ni][1] = *reinterpret_cast<const uint32_t*>(&sBlo[(n0 + g) * LDT + kb + 8]);
        }
#pragma unroll
        for (int mi = 0; mi < 2; mi++) {
#pragma unroll
            for (int ni = 0; ni < 8; ni++) {
                mma16816(acc[mi][ni], ah[mi], bh[ni]);
                mma16816(acc[mi][ni], ah[mi], bl[ni]);
                mma16816(acc[mi][ni], al[mi], bh[ni]);
            }
        }
    }
}

// ---------------- dtype detection + batch conversion ---------------------------
__global__ void detect_k(const int* __restrict__ raw, int* __restrict__ flag) {
    int all0 = 1;
    for (int i = 1; i < 64; i += 2)
        if (raw[i] != 0) all0 = 0;
    *flag = all0;
}

__global__ void conv_k(const int* __restrict__ raw, int* __restrict__ dst, int n,
                       const int* __restrict__ flag) {
    int i = blockIdx.x * blockDim.x + threadIdx.x;
    if (i < n) dst[i] = (*flag) ? raw[2 * i] : raw[i];
}

// ---------------- tiny utilities ----------------------------------------------
__global__ void zero4_k(float* __restrict__ d, int n4) {
    int i = blockIdx.x * blockDim.x + threadIdx.x;
    if (i < n4) reinterpret_cast<float4*>(d)[i] = make_float4(0.f, 0.f, 0.f, 0.f);
}

__global__ void zero_int_k(int* __restrict__ d, int n) {
    int i = blockIdx.x * blockDim.x + threadIdx.x;
    if (i < n) d[i] = 0;
}

// ---------------- graph counts -------------------------------------------------
__global__ void count_k(const int* __restrict__ batch, int* __restrict__ cnt) {
    __shared__ int bins[N_GRAPHS];
    if (threadIdx.x < N_GRAPHS) bins[threadIdx.x] = 0;
    __syncthreads();
    int i = blockIdx.x * blockDim.x + threadIdx.x;
    if (i < N_NODES) {
        unsigned g = (unsigned)batch[i];
        if (g < N_GRAPHS) atomicAdd(&bins[g], 1);
    }
    __syncthreads();
    if (threadIdx.x < N_GRAPHS) atomicAdd(&cnt[threadIdx.x], bins[threadIdx.x]);
}

__global__ void rcnt_k(const int* __restrict__ cnt, float* __restrict__ rcnt) {
    int g = threadIdx.x;
    if (g < N_GRAPHS) rcnt[g] = 1.f / fmaxf((float)cnt[g], 1.0f);
}

// ---------------- CSR build (reads raw edge buffer with dtype flag) -----------
__global__ void hist_k(const int* __restrict__ raw, const int* __restrict__ flag,
                       int* __restrict__ indeg) {
    int e = blockIdx.x * blockDim.x + threadIdx.x;
    if (e >= N_EDGES) return;
    int f = *flag;
    unsigned dst = (unsigned)raw[f ? 2 * (N_EDGES + e) : (N_EDGES + e)];
    if (dst < N_NODES) atomicAdd(&indeg[dst], 1);
}

__global__ void scan1_k(const int* __restrict__ indeg, int* __restrict__ rowptr,
                        int* __restrict__ blocksum) {
    __shared__ int s[SCAN_BLK];
    int t = threadIdx.x;
    int i = blockIdx.x * SCAN_BLK + t;
    int v = (i < N_NODES) ? indeg[i] : 0;
    s[t] = v;
    __syncthreads();
#pragma unroll
    for (int off = 1; off < SCAN_BLK; off <<= 1) {
        int tmp = (t >= off) ? s[t - off] : 0;
        __syncthreads();
        s[t] += tmp;
        __syncthreads();
    }
    if (i < N_NODES) rowptr[i] = s[t] - v;
    if (t == SCAN_BLK - 1) blocksum[blockIdx.x] = s[t];
}

__global__ void scan2_k(const int* __restrict__ blocksum, int* __restrict__ blockoff,
                        int* __restrict__ rowptr) {
    if (threadIdx.x == 0) {
        int acc = 0;
        for (int b = 0; b < SCAN_NBLK; b++) {
            blockoff[b] = acc;
            acc += blocksum[b];
        }
        rowptr[N_NODES] = acc;
    }
}

__global__ void scan3_k(int* __restrict__ rowptr, int* __restrict__ cursor,
                        const int* __restrict__ blockoff) {
    int i = blockIdx.x * blockDim.x + threadIdx.x;
    if (i < N_NODES) {
        int v = rowptr[i] + blockoff[i / SCAN_BLK];
        rowptr[i] = v;
        cursor[i] = v;
    }
}

__global__ void fill_k(const int* __restrict__ raw, const int* __restrict__ flag,
                       int* __restrict__ cursor, int* __restrict__ col) {
    int e = blockIdx.x * blockDim.x + threadIdx.x;
    if (e >= N_EDGES) return;
    int f = *flag;
    unsigned src = (unsigned)raw[f ? 2 * e : e];
    unsigned dst = (unsigned)raw[f ? 2 * (N_EDGES + e) : (N_EDGES + e)];
    if (src >= N_NODES || dst >= N_NODES) return;
    int pos = atomicAdd(&cursor[dst], 1);
    col[pos] = (int)src;
}

// ---------------- weight prep: W[K,N] -> split bf16 W^T [N][K] row-major ------
__global__ void prep_w_k(const float* __restrict__ gw1, const float* __restrict__ gw2) {
    int w = blockIdx.x >> 5;           // 0..7
    int chunk = blockIdx.x & 31;       // 0..31: 512 elements each
    const float* W = (w < 4) ? (gw1 + w * D * D) : (gw2 + (w - 4) * D * D);
    __nv_bfloat16* hi = g_wprep + (size_t)(w * 2 + 0) * D * D;
    __nv_bfloat16* lo = g_wprep + (size_t)(w * 2 + 1) * D * D;
    for (int idx = chunk * 512 + threadIdx.x; idx < (chunk + 1) * 512; idx += blockDim.x) {
        int n = idx >> 7;
        int k = idx & 127;
        float x = W[k * D + n];
        __nv_bfloat16 h = __float2bfloat16_rn(x);
        float r = x - __bfloat162float(h);
        hi[n * D + k] = h;
        lo[n * D + k] = __float2bfloat16_rn(r);
    }
}

// ---------------- fused gather + double GEMM + GraphNorm stats ----------------
// outp = relu(relu((h + gather(h))@W1+b1)@W2+b2); accumulates per-graph SUM/SUMSQ.
// hin and outp MUST be different buffers (cross-CTA gather reads hin).
#define GEMM_SMEM (4 * 128 * LDT * 2 + 512)
__global__ void __launch_bounds__(256, 1)
gemm_fused_k(const float* __restrict__ hin,
             const int* __restrict__ rowptr, const int* __restrict__ col,
             const __nv_bfloat16* __restrict__ Wp1, const float* __restrict__ b1,
             const __nv_bfloat16* __restrict__ Wp2, const float* __restrict__ b2,
             float* __restrict__ outp, const int* __restrict__ batch,
             float* __restrict__ stats) {
    extern __shared__ __nv_bfloat16 sm[];
    __nv_bfloat16* sBhi = sm;
    __nv_bfloat16* sBlo = sm + 128 * LDT;
    __nv_bfloat16* sAhi = sm + 2 * 128 * LDT;
    __nv_bfloat16* sAlo = sm + 3 * 128 * LDT;
    float* stage = reinterpret_cast<float*>(sm);                       // 128*STP*4 = 67584 B
    int* gl = reinterpret_cast<int*>((char*)sm + 4 * 128 * LDT * 2);   // 128 ints

    int tid = threadIdx.x;
    int wid = tid >> 5;
    int lid = tid & 31;
    int g = lid >> 2;
    int t = lid & 3;
    int wm = wid >> 1;
    int wn = wid & 1;
    int mbase = blockIdx.x * 128;

    // graph ids for this row block
    if (tid < 128) {
        int grow = mbase + tid;
        gl[tid] = (grow < N_NODES) ? (batch[grow] & (N_GRAPHS - 1)) : -1;
    }

    // ---- phase 0a: W1 -> sB ----
    {
        const uint4* wsrc = reinterpret_cast<const uint4*>(Wp1);
#pragma unroll 4
        for (int i = tid; i < 4096; i += 256) {
            uint4 v = wsrc[i];
            int m = i & 2047;
            int row = m >> 4;
            int c8 = (m & 15) * 8;
            __nv_bfloat16* dst = (i < 2048) ? sBhi : sBlo;
            *reinterpret_cast<uint4*>(&dst[row * LDT + c8]) = v;
        }
    }

    // ---- phase 0b: fused CSR gather + split-convert -> sA (warp per row) ----
    for (int rr = 0; rr < 16; rr++) {
        int row = wid * 16 + rr;
        int grow = mbase + row;
        float4 acc = make_float4(0.f, 0.f, 0.f, 0.f);
        if (grow < N_NODES) {
            acc = __ldg(reinterpret_cast<const float4*>(&hin[(size_t)grow * D + lid * 4]));
            int p0 = __ldg(&rowptr[grow]);
            int p1 = __ldg(&rowptr[grow + 1]);
            int p = p0;
            for (; p + 3 < p1; p += 4) {
                int s0 = __ldg(&col[p]);
                int s1 = __ldg(&col[p + 1]);
                int s2 = __ldg(&col[p + 2]);
                int s3 = __ldg(&col[p + 3]);
                float4 v0 = __ldg(reinterpret_cast<const float4*>(&hin[(size_t)s0 * D + lid * 4]));
                float4 v1 = __ldg(reinterpret_cast<const float4*>(&hin[(size_t)s1 * D + lid * 4]));
                float4 v2 = __ldg(reinterpret_cast<const float4*>(&hin[(size_t)s2 * D + lid * 4]));
                float4 v3 = __ldg(reinterpret_cast<const float4*>(&hin[(size_t)s3 * D + lid * 4]));
                acc.x += (v0.x + v1.x) + (v2.x + v3.x);
                acc.y += (v0.y + v1.y) + (v2.y + v3.y);
                acc.z += (v0.z + v1.z) + (v2.z + v3.z);
                acc.w += (v0.w + v1.w) + (v2.w + v3.w);
            }
            for (; p < p1; p++) {
                int s0 = __ldg(&col[p]);
                float4 v0 = __ldg(reinterpret_cast<const float4*>(&hin[(size_t)s0 * D + lid * 4]));
                acc.x += v0.x; acc.y += v0.y; acc.z += v0.z; acc.w += v0.w;
            }
        }
        // split to hi/lo bf16 and store 8B per lane
        __nv_bfloat16 h0 = __float2bfloat16_rn(acc.x);
        __nv_bfloat16 h1 = __float2bfloat16_rn(acc.y);
        __nv_bfloat16 h2 = __float2bfloat16_rn(acc.z);
        __nv_bfloat16 h3 = __float2bfloat16_rn(acc.w);
        uint2 hu, lu;
        hu.x = pack_bf16(h0, h1);
        hu.y = pack_bf16(h2, h3);
        lu.x = pack_bf16(__float2bfloat16_rn(acc.x - __bfloat162float(h0)),
                         __float2bfloat16_rn(acc.y - __bfloat162float(h1)));
        lu.y = pack_bf16(__float2bfloat16_rn(acc.z - __bfloat162float(h2)),
                         __float2bfloat16_rn(acc.w - __bfloat162float(h3)));
        *reinterpret_cast<uint2*>(&sAhi[row * LDT + lid * 4]) = hu;
        *reinterpret_cast<uint2*>(&sAlo[row * LDT + lid * 4]) = lu;
    }
    __syncthreads();

    // ---- mainloop 1 ----
    float acc[2][8][4];
#pragma unroll
    for (int mi = 0; mi < 2; mi++)
#pragma unroll
        for (int ni = 0; ni < 8; ni++)
#pragma unroll
            for (int q = 0; q < 4; q++) acc[mi][ni][q] = 0.f;
    mma_loop(sAhi, sAlo, sBhi, sBlo, wm, wn, g, t, acc);
    __syncthreads();

    // ---- phase 2: C = relu(acc+b1) split into sA; W2 -> sB ----
#pragma unroll
    for (int mi = 0; mi < 2; mi++) {
#pragma unroll
        for (int ni = 0; ni < 8; ni++) {
            int c0 = wn * 64 + ni * 8 + t * 2;
            float bb0 = __ldg(&b1[c0]);
            float bb1 = __ldg(&b1[c0 + 1]);
#pragma unroll
            for (int rr = 0; rr < 2; rr++) {
                int row = wm * 32 + mi * 16 + g + rr * 8;
                float v0 = fmaxf(acc[mi][ni][rr * 2 + 0] + bb0, 0.f);
                float v1 = fmaxf(acc[mi][ni][rr * 2 + 1] + bb1, 0.f);
                __nv_bfloat16 h0 = __float2bfloat16_rn(v0);
                __nv_bfloat16 h1 = __float2bfloat16_rn(v1);
                float r0 = v0 - __bfloat162float(h0);
                float r1 = v1 - __bfloat162float(h1);
                *reinterpret_cast<uint32_t*>(&sAhi[row * LDT + c0]) = pack_bf16(h0, h1);
                *reinterpret_cast<uint32_t*>(&sAlo[row * LDT + c0]) =
                    pack_bf16(__float2bfloat16_rn(r0), __float2bfloat16_rn(r1));
            }
        }
    }
    {
        const uint4* wsrc = reinterpret_cast<const uint4*>(Wp2);
#pragma unroll 4
        for (int i = tid; i < 4096; i += 256) {
            uint4 v = wsrc[i];
            int m = i & 2047;
            int row = m >> 4;
            int c8 = (m & 15) * 8;
            __nv_bfloat16* dst = (i < 2048) ? sBhi : sBlo;
            *reinterpret_cast<uint4*>(&dst[row * LDT + c8]) = v;
        }
    }
    __syncthreads();

    // ---- mainloop 2 ----
#pragma unroll
    for (int mi = 0; mi < 2; mi++)
#pragma unroll
        for (int ni = 0; ni < 8; ni++)
#pragma unroll
            for (int q = 0; q < 4; q++) acc[mi][ni][q] = 0.f;
    mma_loop(sAhi, sAlo, sBhi, sBlo, wm, wn, g, t, acc);
    __syncthreads();   // sB/sA dead; stage may overwrite

    // ---- phase 3: stage relu(acc+b2) ----
#pragma unroll
    for (int mi = 0; mi < 2; mi++) {
#pragma unroll
        for (int ni = 0; ni < 8; ni++) {
            int c0 = wn * 64 + ni * 8 + t * 2;
            float bb0 = __ldg(&b2[c0]);
            float bb1 = __ldg(&b2[c0 + 1]);
#pragma unroll
            for (int rr = 0; rr < 2; rr++) {
                int row = wm * 32 + mi * 16 + g + rr * 8;
                stage[row * STP + c0] = fmaxf(acc[mi][ni][rr * 2 + 0] + bb0, 0.f);
                stage[row * STP + c0 + 1] = fmaxf(acc[mi][ni][rr * 2 + 1] + bb1, 0.f);
            }
        }
    }
    __syncthreads();

    // ---- phase 4a: per-graph stats (sorted batch, flush on change) ----
    {
        int colf = tid >> 1;
        int rbeg = (tid & 1) * 64;
        int gcur = gl[rbeg];
        float s = 0.f, q = 0.f;
        if (gcur >= 0) {
            for (int r = rbeg; r < rbeg + 64; r++) {
                int gg = gl[r];
                if (gg < 0) break;
                if (gg != gcur) {
                    atomicAdd(&stats[gcur * D + colf], s);
                    atomicAdd(&stats[N_GRAPHS * D + gcur * D + colf], q);
                    s = 0.f; q = 0.f;
                    gcur = gg;
                }
                float v = stage[r * STP + colf];
                s += v;
                q = fmaf(v, v, q);
            }
            atomicAdd(&stats[gcur * D + colf], s);
            atomicAdd(&stats[N_GRAPHS * D + gcur * D + colf], q);
        }
    }

    // ---- phase 4b: coalesced fp32 output ----
    for (int i = tid; i < 4096; i += 256) {
        int row = i >> 5;
        int c4 = (i & 31) * 4;
        int grow = mbase + row;
        if (grow < N_NODES) {
            float4 v = *reinterpret_cast<const float4*>(&stage[row * STP + c4]);
            *reinterpret_cast<float4*>(&outp[(size_t)grow * D + c4]) = v;
        }
    }
}

// ---------------- norm + relu, in place -----------------------------------------
__global__ void norm_k(float* __restrict__ h, const int* __restrict__ batch,
                       const float* __restrict__ stats, const float* __restrict__ rcnt,
                       const float* __restrict__ weight, const float* __restrict__ bias,
                       const float* __restrict__ scale) {
    const float* SUM = stats;
    const float* SQ = stats + N_GRAPHS * D;
    int idx = blockIdx.x * blockDim.x + threadIdx.x;
    if (idx >= N_NODES * D) return;
    int r = idx >> 7;
    int f = idx & 127;
    int g = batch[r] & (N_GRAPHS - 1);
    float rc = rcnt[g];
    float sc = scale[f];
    float mean = SUM[g * D + f] * rc;
    float q = SQ[g * D + f] * rc;
    float var = q - mean * mean * sc * (2.f - sc);
    var = fmaxf(var, 0.f);
    float o = weight[f] * (h[idx] - mean * sc) * rsqrtf(var + GN_EPS) + bias[f];
    h[idx] = fmaxf(o, 0.f);
}

// ---------------- readout segment sum ------------------------------------------
#define SEG_ROWS 128
__global__ void seg_sum_k(const float* __restrict__ h, const int* __restrict__ batch,
                          float* __restrict__ out) {
    int f = threadIdx.x;
    int r0 = blockIdx.x * SEG_ROWS;
    if (r0 >= N_NODES) return;
    int r1 = min(r0 + SEG_ROWS, N_NODES);
    int gcur = batch[r0] & (N_GRAPHS - 1);
    float acc = 0.f;
    for (int r = r0; r < r1; r++) {
        int g = batch[r] & (N_GRAPHS - 1);
        if (g != gcur) {
            atomicAdd(&out[gcur * D + f], acc);
            acc = 0.f;
            gcur = g;
        }
        acc += h[r * D + f];
    }
    atomicAdd(&out[gcur * D + f], acc);
}

// ---------------- final MLP -----------------------------------------------------
__global__ void mlp_relu_k(const float* __restrict__ in, const float* __restrict__ W,
                           const float* __restrict__ b, float* __restrict__ outp) {
    __shared__ float row[D];
    int g = blockIdx.x, j = threadIdx.x;
    row[j] = in[g * D + j];
    __syncthreads();
    float acc = b[j];
#pragma unroll
    for (int k = 0; k < D; k++) acc = fmaf(row[k], W[k * D + j], acc);
    outp[g * D + j] = fmaxf(acc, 0.f);
}

__global__ void final_k(const float* __restrict__ in, const float* __restrict__ W,
                        const float* __restrict__ b, float* __restrict__ outp) {
    __shared__ float row[D];
    __shared__ float logits[N_CLASSES];
    __shared__ float red[2];
    int g = blockIdx.x, t = threadIdx.x;
    row[t] = in[g * D + t];
    __syncthreads();
    if (t < N_CLASSES) {
        float acc = b[t];
#pragma unroll
        for (int k = 0; k < D; k++) acc = fmaf(row[k], W[k * N_CLASSES + t], acc);
        logits[t] = acc;
    }
    __syncthreads();
    if (t == 0) {
        float m = -1e30f;
        for (int c = 0; c < N_CLASSES; c++) m = fmaxf(m, logits[c]);
        float s = 0.f;
        for (int c = 0; c < N_CLASSES; c++) s += expf(logits[c] - m);
        red[0] = m;
        red[1] = logf(s);
    }
    __syncthreads();
    if (t < N_CLASSES) outp[g * N_CLASSES + t] = logits[t] - red[0] - red[1];
}

// ---------------- launch --------------------------------------------------------
extern "C" void kernel_launch(void* const* d_in, const int* in_sizes, int n_in,
                              void* d_out, int out_size) {
    const float* x    = (const float*)d_in[0];
    const float* gw1  = (const float*)d_in[1];
    const float* gb1  = (const float*)d_in[2];
    const float* gw2  = (const float*)d_in[3];
    const float* gb2  = (const float*)d_in[4];
    const float* gnw  = (const float*)d_in[5];
    const float* gnb  = (const float*)d_in[6];
    const float* gns  = (const float*)d_in[7];
    const float* fw1  = (const float*)d_in[8];
    const float* fb1  = (const float*)d_in[9];
    const float* fw2  = (const float*)d_in[10];
    const float* fb2  = (const float*)d_in[11];
    const float* fw3  = (const float*)d_in[12];
    const float* fb3  = (const float*)d_in[13];
    const int*   edge_raw  = (const int*)d_in[14];
    const int*   batch_raw = (const int*)d_in[15];
    float* out = (float*)d_out;

    float *A, *B, *STATS, *RCNT, *GSUM, *M1, *M2;
    int *CNT, *BATCH, *FLAG;
    int *INDEG, *ROWPTR, *CURSOR, *COL, *BSUM, *BOFF;
    __nv_bfloat16* WPREP;
    cudaGetSymbolAddress((void**)&A, g_A);
    cudaGetSymbolAddress((void**)&B, g_B);
    cudaGetSymbolAddress((void**)&STATS, g_stats);
    cudaGetSymbolAddress((void**)&CNT, g_cnt);
    cudaGetSymbolAddress((void**)&RCNT, g_rcnt);
    cudaGetSymbolAddress((void**)&GSUM, g_gsum);
    cudaGetSymbolAddress((void**)&M1, g_m1);
    cudaGetSymbolAddress((void**)&M2, g_m2);
    cudaGetSymbolAddress((void**)&BATCH, g_batch);
    cudaGetSymbolAddress((void**)&FLAG, g_is64);
    cudaGetSymbolAddress((void**)&INDEG, g_indeg);
    cudaGetSymbolAddress((void**)&ROWPTR, g_rowptr);
    cudaGetSymbolAddress((void**)&CURSOR, g_cursor);
    cudaGetSymbolAddress((void**)&COL, g_col);
    cudaGetSymbolAddress((void**)&BSUM, g_blocksum);
    cudaGetSymbolAddress((void**)&BOFF, g_blockoff);
    cudaGetSymbolAddress((void**)&WPREP, g_wprep);

    cudaFuncSetAttribute(gemm_fused_k, cudaFuncAttributeMaxDynamicSharedMemorySize, GEMM_SMEM);

    const int statall4 = L_LAYERS * 2 * N_GRAPHS * D / 4;
    const int gsum4 = N_GRAPHS * D / 4;
    const int seg_blocks = (N_NODES + SEG_ROWS - 1) / SEG_ROWS;
    const int gemm_blocks = (N_NODES + 127) / 128;
    const int norm_grid = (N_NODES * D + 255) / 256;
    const int egrid = (N_EDGES + 255) / 256;
    const int ngrid = (N_NODES + 255) / 256;

    // dtype canonicalization (batch only; edges read raw with flag)
    detect_k<<<1, 1>>>(edge_raw, FLAG);
    conv_k<<<ngrid, 256>>>(batch_raw, BATCH, N_NODES, FLAG);

    // weight prep
    prep_w_k<<<256, 256>>>(gw1, gw2);

    // zero all per-layer stats + readout buffer upfront
    zero4_k<<<(statall4 + 255) / 256, 256>>>(STATS, statall4);
    zero4_k<<<(gsum4 + 255) / 256, 256>>>(GSUM, gsum4);

    // CSR build
    zero_int_k<<<ngrid, 256>>>(INDEG, N_NODES);
    hist_k<<<egrid, 256>>>(edge_raw, FLAG, INDEG);
    scan1_k<<<SCAN_NBLK, SCAN_BLK>>>(INDEG, ROWPTR, BSUM);
    scan2_k<<<1, 32>>>(BSUM, BOFF, ROWPTR);
    scan3_k<<<ngrid, 256>>>(ROWPTR, CURSOR, BOFF);
    fill_k<<<egrid, 256>>>(edge_raw, FLAG, CURSOR, COL);

    // graph counts
    zero_int_k<<<1, N_GRAPHS>>>(CNT, N_GRAPHS);
    count_k<<<ngrid, 256>>>(BATCH, CNT);
    rcnt_k<<<1, N_GRAPHS>>>(CNT, RCNT);

    // ping-pong: x->A, A->B, B->A, A->B  (gather reads hin, writes other buffer)
    const float* hin = x;
    for (int l = 0; l < L_LAYERS; l++) {
        const float* b1 = gb1 + l * D;
        const float* b2 = gb2 + l * D;
        const float* nw = gnw + l * D;
        const float* nb = gnb + l * D;
        const float* ns = gns + l * D;
        const __nv_bfloat16* wp1 = WPREP + (size_t)(2 * l) * D * D;       // W1[l] hi||lo
        const __nv_bfloat16* wp2 = WPREP + (size_t)(2 * (4 + l)) * D * D; // W2[l] hi||lo
        float* stats_l = STATS + (size_t)l * 2 * N_GRAPHS * D;
        float* hout = (l & 1) ? B : A;

        gemm_fused_k<<<gemm_blocks, 256, GEMM_SMEM>>>(hin, ROWPTR, COL, wp1, b1, wp2, b2,
                                                      hout, BATCH, stats_l);
        norm_k<<<norm_grid, 256>>>(hout, BATCH, stats_l, RCNT, nw, nb, ns);
        hin = hout;
    }

    // readout + MLP head (final buffer = B for L_LAYERS=4)
    seg_sum_k<<<seg_blocks, D>>>(B, BATCH, GSUM);
    mlp_relu_k<<<N_GRAPHS, D>>>(GSUM, fw1, fb1, M1);
    mlp_relu_k<<<N_GRAPHS, D>>>(M1, fw2, fb2, M2);
    final_k<<<N_GRAPHS, D>>>(M2, fw3, fb3, out);
}